// round 16
// baseline (speedup 1.0000x reference)
#include <cuda_runtime.h>
#include <cstdint>
#include <cstddef>

typedef unsigned long long u64;

// ---- packed f32x2 helpers (Blackwell sm_103a) ----
#define FMA2(d, a, b, c) asm("fma.rn.f32x2 %0, %1, %2, %3;" : "=l"(d) : "l"(a), "l"(b), "l"(c))
#define MUL2(d, a, b)    asm("mul.rn.f32x2 %0, %1, %2;"     : "=l"(d) : "l"(a), "l"(b))
#define ADD2(d, a, b)    asm("add.rn.f32x2 %0, %1, %2;"     : "=l"(d) : "l"(a), "l"(b))

__device__ __forceinline__ u64 pack2(float lo, float hi) {
    u64 r; asm("mov.b64 %0, {%1, %2};" : "=l"(r) : "f"(lo), "f"(hi)); return r;
}
__device__ __forceinline__ float2 unpack2(u64 v) {
    float2 r; asm("mov.b64 {%0, %1}, %2;" : "=f"(r.x), "=f"(r.y) : "l"(v)); return r;
}
__device__ __forceinline__ void stg_cs_v4(float* p, float4 v) {
    asm volatile("st.global.cs.v4.f32 [%0], {%1, %2, %3, %4};"
                 :: "l"(p), "f"(v.x), "f"(v.y), "f"(v.z), "f"(v.w) : "memory");
}
__device__ __forceinline__ uint32_t smem_u32(const void* p) {
    uint32_t a;
    asm("{ .reg .u64 t; cvta.to.shared.u64 t, %1; cvt.u32.u64 %0, t; }" : "=r"(a) : "l"(p));
    return a;
}
__device__ __forceinline__ void mbar_init(uint32_t mbar, uint32_t cnt) {
    asm volatile("mbarrier.init.shared.b64 [%0], %1;" :: "r"(mbar), "r"(cnt) : "memory");
}
__device__ __forceinline__ void mbar_expect_tx(uint32_t mbar, uint32_t bytes) {
    asm volatile("mbarrier.arrive.expect_tx.shared.b64 _, [%0], %1;" :: "r"(mbar), "r"(bytes) : "memory");
}
__device__ __forceinline__ void bulk_g2s(uint32_t dst, const void* src, uint32_t bytes, uint32_t mbar) {
    asm volatile("cp.async.bulk.shared::cta.global.mbarrier::complete_tx::bytes [%0], [%1], %2, [%3];"
                 :: "r"(dst), "l"(src), "r"(bytes), "r"(mbar) : "memory");
}
__device__ __forceinline__ void mbar_wait(uint32_t mbar, uint32_t parity) {
    asm volatile(
        "{\n\t"
        ".reg .pred P1;\n\t"
        "WL_%=:\n\t"
        "mbarrier.try_wait.parity.acquire.cta.shared::cta.b64 P1, [%0], %1, 0x989680;\n\t"
        "@P1 bra.uni WD_%=;\n\t"
        "bra.uni WL_%=;\n\t"
        "WD_%=:\n\t"
        "}"
        :: "r"(mbar), "r"(parity) : "memory");
}

constexpr int E_DIM = 1024;

// ============================================================================
// Fused: h = x@w1^T + b1 ; q = Pauli-Z cosine strings ; out = q@w2^T + b2
//   q0=c0, q1=c1, q2=c0c2, q3=c1c3, q4=c0c2c4, q5=c1c3c5, q6=c0c2c4c6,
//   q7=c0..c7  with c_i = cos(h_i)
//
// R15 (one-wave balanced partitioning, 2-slot TMA ring, deferred q, w2 tail)
// + XOR-PERMUTED pair assignment in the butterfly: lane loads
// wpk[j] = f-pair (j ^ perm), perm = (lane>>3)&3. Pair IDs then align
// automatically across shfl partners, so the value-halving reduction is
//   v0 += shfl(v2,16); v1 += shfl(v3,16); w = v0 + shfl(v1,8); xor4/2/1
// with ZERO select instructions (was 12 SELs per warp-row).
// Lane 8p ends holding pair p fully summed (same store pattern as before).
// ============================================================================
constexpr int SROWS   = 4;                   // rows per pipeline stage
constexpr int NSLOT   = 2;                   // ring depth
constexpr int MAXR    = 56;                  // max rows per block (14 groups)
constexpr int STBYTES = SROWS * E_DIM * 4;   // 16384

__global__ void __launch_bounds__(256, 4)
ffq_fused(const float* __restrict__ x,  const float* __restrict__ w1,
          const float* __restrict__ b1, const float* __restrict__ w2,
          const float* __restrict__ b2, float* __restrict__ out, int ngroups)
{
    __shared__ __align__(128) float xs[NSLOT][SROWS * E_DIM];  // 32 KB ring
    __shared__ __align__(16) float s_part[MAXR][8][8];         // 14 KB
    __shared__ __align__(16) float s_q[MAXR][8];               // 1.75 KB
    __shared__ __align__(8) u64 mbar_s[NSLOT];

    const int tid  = threadIdx.x;
    const int warp = tid >> 5;
    const int lane = tid & 31;
    const int perm = (lane >> 3) & 3;        // XOR pair-permutation id

    const uint32_t mb0 = smem_u32(&mbar_s[0]);
    const uint32_t xs0 = smem_u32(&xs[0][0]);

    // balanced group range for this block
    const int g0     = (int)(((long long)ngroups * blockIdx.x)       / gridDim.x);
    const int g1     = (int)(((long long)ngroups * (blockIdx.x + 1)) / gridDim.x);
    const int nstage = g1 - g0;              // 13 or 14
    const int nrows  = nstage * SROWS;       // 52 or 56
    const int block_row0 = g0 * SROWS;

    // ---- [A] phase-1 weights: wpk[j] = f-pair (j ^ perm) ----
    const int e1 = warp * 128 + lane * 4;
    u64 wpk[4][4];
#pragma unroll
    for (int j = 0; j < 4; j++) {
        const int pr = j ^ perm;
        const float* w0 = w1 + (2 * pr)     * E_DIM + e1;
        const float* w1r= w1 + (2 * pr + 1) * E_DIM + e1;
#pragma unroll
        for (int e = 0; e < 4; e++)
            wpk[j][e] = pack2(w0[e], w1r[e]);
    }
    const float bf = b1[tid & 7];

    if (tid == 0) {
#pragma unroll
        for (int k = 0; k < NSLOT; k++) mbar_init(mb0 + k * 8, 1);
    }
    __syncthreads();

    const float* src = x + (size_t)block_row0 * E_DIM;

    // prime the ring
    if (tid == 0) {
#pragma unroll
        for (int k = 0; k < NSLOT; k++) {
            mbar_expect_tx(mb0 + k * 8, STBYTES);
            bulk_g2s(xs0 + k * STBYTES, src + (size_t)k * SROWS * E_DIM,
                     STBYTES, mb0 + k * 8);
        }
    }

    for (int s = 0; s < nstage; s++) {
        const int slot = s & (NSLOT - 1);
        mbar_wait(mb0 + slot * 8, (s >> 1) & 1);

#pragma unroll
        for (int r = 0; r < SROWS; r++) {
            float4 xv = *reinterpret_cast<const float4*>(
                &xs[slot][r * E_DIM + e1]);
            u64 xd[4];
            xd[0] = pack2(xv.x, xv.x);
            xd[1] = pack2(xv.y, xv.y);
            xd[2] = pack2(xv.z, xv.z);
            xd[3] = pack2(xv.w, xv.w);

            u64 v0, v1, v2, v3;
            MUL2(v0, xd[0], wpk[0][0]);
            MUL2(v1, xd[0], wpk[1][0]);
            MUL2(v2, xd[0], wpk[2][0]);
            MUL2(v3, xd[0], wpk[3][0]);
#pragma unroll
            for (int e = 1; e < 4; e++) {
                FMA2(v0, xd[e], wpk[0][e], v0);
                FMA2(v1, xd[e], wpk[1][e], v1);
                FMA2(v2, xd[e], wpk[2][e], v2);
                FMA2(v3, xd[e], wpk[3][e], v3);
            }

            // SEL-free butterfly (pair IDs aligned by XOR perm):
            // xor16: partner's v2,v3 carry exactly my v0,v1's pairs
            {
                u64 r0 = __shfl_xor_sync(0xffffffffu, v2, 16);
                u64 r1 = __shfl_xor_sync(0xffffffffu, v3, 16);
                ADD2(v0, v0, r0);
                ADD2(v1, v1, r1);
            }
            // xor8: partner's v1 carries my v0's pair
            u64 w;
            {
                u64 r2 = __shfl_xor_sync(0xffffffffu, v1, 8);
                ADD2(w, v0, r2);
            }
            // xor4 / xor2 / xor1: plain u64 reductions
            {
                u64 rv = __shfl_xor_sync(0xffffffffu, w, 4);
                ADD2(w, w, rv);
                rv = __shfl_xor_sync(0xffffffffu, w, 2);
                ADD2(w, w, rv);
                rv = __shfl_xor_sync(0xffffffffu, w, 1);
                ADD2(w, w, rv);
            }
            // lane 8p holds pair p fully summed (p == perm there)
            if ((lane & 7) == 0) {
                *reinterpret_cast<u64*>(
                    &s_part[s * SROWS + r][warp][2 * perm]) = w;
            }
        }
        __syncthreads();   // slot drained; s_part row-group committed

        if (tid == 0 && s + NSLOT < nstage) {
            mbar_expect_tx(mb0 + slot * 8, STBYTES);
            bulk_g2s(xs0 + slot * STBYTES,
                     src + (size_t)(s + NSLOT) * SROWS * E_DIM,
                     STBYTES, mb0 + slot * 8);
        }
    }

    // ---- [B] q epilogue: nrows x 8 f <= 448 items, 2 per thread ----
#pragma unroll
    for (int it = 0; it < 2; it++) {
        const int item  = it * 256 + tid;
        const bool valid = item < nrows * 8;
        const int r  = valid ? (item >> 3) : 0;
        const int ff = item & 7;          // == tid & 7, matches bf

        float h = bf;
#pragma unroll
        for (int w = 0; w < 8; w++) h += s_part[r][w][ff];
        float c = __cosf(h);

        // all lanes participate in the shfl (inactive lanes carry junk)
        const int base = lane & 24;
        float cs[8];
#pragma unroll
        for (int jj = 0; jj < 8; jj++)
            cs[jj] = __shfl_sync(0xffffffffu, c, base + jj);

        float q;
        if (ff == 7) {
            q = cs[0]*cs[1]*cs[2]*cs[3]*cs[4]*cs[5]*cs[6]*cs[7];
        } else {
            q = 1.0f;
#pragma unroll
            for (int jj = 0; jj < 8; jj++)
                if (jj <= ff && ((jj ^ ff) & 1) == 0) q *= cs[jj];
        }
        if (valid) s_q[r][ff] = q;
    }
    __syncthreads();

    // ---- [C] out tail: w2 f-pairs in regs (loaded after w1 regs die) ----
    const int e2 = tid * 4;
    u64 wp[4][4];
#pragma unroll
    for (int i = 0; i < 4; i++) {
        ulonglong2 v0 = *reinterpret_cast<const ulonglong2*>(w2 + (e2 + i) * 8);
        ulonglong2 v1 = *reinterpret_cast<const ulonglong2*>(w2 + (e2 + i) * 8 + 4);
        wp[i][0] = v0.x; wp[i][1] = v0.y;
        wp[i][2] = v1.x; wp[i][3] = v1.y;
    }
    u64 binit[4];
    {
        float4 bv = *reinterpret_cast<const float4*>(b2 + e2);
        binit[0] = pack2(bv.x, 0.f);
        binit[1] = pack2(bv.y, 0.f);
        binit[2] = pack2(bv.z, 0.f);
        binit[3] = pack2(bv.w, 0.f);
    }

    float* orow = out + (size_t)block_row0 * E_DIM + e2;
#pragma unroll 4
    for (int r = 0; r < nrows; r++) {
        ulonglong2 qv0 = *reinterpret_cast<const ulonglong2*>(&s_q[r][0]);
        ulonglong2 qv1 = *reinterpret_cast<const ulonglong2*>(&s_q[r][4]);

        float o[4];
#pragma unroll
        for (int i = 0; i < 4; i++) {
            u64 acc = binit[i];
            FMA2(acc, qv0.x, wp[i][0], acc);
            FMA2(acc, qv0.y, wp[i][1], acc);
            FMA2(acc, qv1.x, wp[i][2], acc);
            FMA2(acc, qv1.y, wp[i][3], acc);
            float2 t = unpack2(acc);
            o[i] = t.x + t.y;
        }
        stg_cs_v4(orow, make_float4(o[0], o[1], o[2], o[3]));
        orow += E_DIM;
    }
}

extern "C" void kernel_launch(void* const* d_in, const int* in_sizes, int n_in,
                              void* d_out, int out_size) {
    const float* x  = (const float*)d_in[0];
    const float* w1 = (const float*)d_in[1];
    const float* b1 = (const float*)d_in[2];
    const float* w2 = (const float*)d_in[3];
    const float* b2 = (const float*)d_in[4];
    float* out = (float*)d_out;

    int nsm = 148;
    cudaDeviceGetAttribute(&nsm, cudaDevAttrMultiProcessorCount, 0);
    const int grid = 4 * nsm;                    // one CTA per residency slot

    const int rows    = in_sizes[0] / E_DIM;     // 32768
    const int ngroups = rows / SROWS;            // 8192 four-row groups
    ffq_fused<<<grid, 256>>>(x, w1, b1, w2, b2, out, ngroups);
}